// round 17
// baseline (speedup 1.0000x reference)
#include <cuda_runtime.h>
#include <cstdint>

// Shapes: x[8,64,512,512] f32, W[64,64], b[64], seg_w[4,4] -> out[8,64,512,512]
// SEG=4 -> 128x128 blocks. A "band" = one (b,c,i) slab of 128 rows = 16384 float4.
// Measured ceilings: read ~6.9 TB/s (pool 77.9us), write ~6.9 TB/s effective
// (bcast 78.0us), linear ~1.5us, fixed harness ~16us -> floor ~173us.
// Structure: R1's three kernels + PDL chaining (launch staging; memory
// ordering via cudaGridDependencySynchronize = full producer completion).
#define Bb 8
#define Cc 64
#define Oo 64
#define BAND_F4 16384
#define NBAND   2048

// scratch (__device__ globals: allocation-free rule)
__device__ float g_pooled[Bb*Cc*16];     // [b][c][i*4+j], mean-scaled
__device__ float g_weighted[Bb*Oo*16];   // [b][o][i*4+j]

// ---------------------------------------------------------------------------
// Kernel 1: segment mean pool (R1 exact hot loop + reduce). One CTA per band.
// PDL trigger placed after the reduce so the streaming/reduce region matches
// the 77.9us build; dependents stage during the store tail + last wave.
// ---------------------------------------------------------------------------
__global__ __launch_bounds__(256) void pool_kernel(const float4* __restrict__ x)
{
    const int g = blockIdx.x;                    // band index 0..2047
    const float4* base = x + (size_t)g * BAND_F4;

    float acc = 0.0f;
    #pragma unroll 8
    for (int idx = threadIdx.x; idx < BAND_F4; idx += 256) {
        float4 v = base[idx];
        acc += (v.x + v.y) + (v.z + v.w);
    }

    #pragma unroll
    for (int off = 16; off; off >>= 1)
        acc += __shfl_xor_sync(0xffffffffu, acc, off);

    cudaTriggerProgrammaticLaunchCompletion();   // launch gate only

    __shared__ float ws[8];
    const int warp = threadIdx.x >> 5;
    if ((threadIdx.x & 31) == 0) ws[warp] = acc; // warp w covers j = w&3
    __syncthreads();

    if (threadIdx.x < 4) {
        const float inv = 1.0f / 16384.0f;
        g_pooled[(g >> 2) * 16 + (g & 3) * 4 + threadIdx.x] =
            (ws[threadIdx.x] + ws[threadIdx.x + 4]) * inv;
    }
}

// ---------------------------------------------------------------------------
// Kernel 2: tiny linear + bias + seg scale. 8192 outputs, hidden under PDL.
// ---------------------------------------------------------------------------
__global__ void __launch_bounds__(256, 8) linear_kernel(
    const float* __restrict__ Wm,
    const float* __restrict__ bias,
    const float* __restrict__ seg_w)
{
    cudaGridDependencySynchronize();             // pool grid complete + visible
    cudaTriggerProgrammaticLaunchCompletion();   // let bcast stage

    const int idx = blockIdx.x * 256 + threadIdx.x;   // 0 .. 8191
    if (idx >= Bb * Oo * 16) return;

    const int ij = idx & 15;
    const int o  = (idx >> 4) & (Oo - 1);
    const int b  = idx >> 10;

    const float* p    = g_pooled + b * (Cc * 16) + ij;
    const float* wrow = Wm + o * Cc;

    float acc = bias[o];
    #pragma unroll
    for (int c = 0; c < Cc; c++)
        acc = fmaf(p[c * 16], wrow[c], acc);

    g_weighted[idx] = acc * seg_w[ij];
}

// ---------------------------------------------------------------------------
// Kernel 3: broadcast (R1 body, plain stores). One CTA per band (b,o,i);
// column segment j loop-invariant; unroll 16 for deeper store pipelining.
// ---------------------------------------------------------------------------
__global__ __launch_bounds__(256) void bcast_kernel(float4* __restrict__ out)
{
    cudaGridDependencySynchronize();             // linear grid complete + visible

    const int g  = blockIdx.x;                   // band index 0..2047
    const int bo = g >> 2;                       // b*O + o
    const int i  = g & 3;

    const float* wv = g_weighted + bo * 16 + i * 4;
    const int j = (threadIdx.x & 127) >> 5;      // fixed per thread
    const float v = wv[j];
    const float4 f = make_float4(v, v, v, v);

    float4* base = out + (size_t)bo * (4 * BAND_F4) + (size_t)i * BAND_F4;

    #pragma unroll 16
    for (int idx = threadIdx.x; idx < BAND_F4; idx += 256)
        base[idx] = f;
}

// ---------------------------------------------------------------------------
// Host: PDL-chained launches (fallback to plain launches if Ex fails).
// ---------------------------------------------------------------------------
template <typename K, typename... Args>
static inline void launch_pdl(K kernel, dim3 grid, bool pdl, Args... args)
{
    cudaLaunchConfig_t cfg = {};
    cfg.gridDim  = grid;
    cfg.blockDim = dim3(256, 1, 1);
    cfg.dynamicSmemBytes = 0;
    cfg.stream = 0;
    cudaLaunchAttribute attr[1];
    if (pdl) {
        attr[0].id = cudaLaunchAttributeProgrammaticStreamSerialization;
        attr[0].val.programmaticStreamSerializationAllowed = 1;
        cfg.attrs = attr;
        cfg.numAttrs = 1;
    }
    cudaError_t e = cudaLaunchKernelEx(&cfg, kernel, args...);
    if (e != cudaSuccess) {                      // fallback: plain launch
        cudaGetLastError();
        kernel<<<grid, 256>>>(args...);
    }
}

extern "C" void kernel_launch(void* const* d_in, const int* in_sizes, int n_in,
                              void* d_out, int out_size)
{
    const float4* x    = (const float4*)d_in[0];
    const float*  Wm   = (const float*)d_in[1];
    const float*  bias = (const float*)d_in[2];
    const float*  segw = (const float*)d_in[3];
    float4* out = (float4*)d_out;

    launch_pdl(pool_kernel,   dim3(NBAND), false, x);
    launch_pdl(linear_kernel, dim3((Bb*Oo*16 + 255) / 256), true, Wm, bias, segw);
    launch_pdl(bcast_kernel,  dim3(NBAND), true, out);
}